// round 14
// baseline (speedup 1.0000x reference)
#include <cuda_runtime.h>

// MultiScaleRoIAlign: 4-level FPN, RoIAlign(aligned=False), OUT=7, SR=2.
// feats: [2,256,200,200],[2,256,100,100],[2,256,50,50],[2,256,25,25] fp32
// boxes: [2,256,4] fp32 -> out: [512,256,7,7] fp32
//
// v14: v13's one-row-per-LDG mapping (warp = bin row ph, lane = (pw, x-tap),
// warp-uniform y-row offsets -> every LDG reads ONE feature row, 1-2 L1
// wavefronts) with a x4 channel unroll: four independent plane streams give
// MLP=16 per warp while geometry stays warp-uniform (regs ~60, ~5 blocks/SM).

#define NLVL 4

__global__ __launch_bounds__(224) void roi_align_kernel(
    const float* __restrict__ f0, const float* __restrict__ f1,
    const float* __restrict__ f2, const float* __restrict__ f3,
    const float* __restrict__ boxes, float* __restrict__ out)
{
    const int blk  = blockIdx.x;
    const int r    = blk >> 2;         // roi 0..511
    const int cq   = blk & 3;          // channel quarter (64 ch)
    const int tid  = threadIdx.x;
    const int ph   = tid >> 5;         // warp 0..6 = bin row
    const int lane = tid & 31;
    const int b    = r >> 8;

    // ---- per-RoI geometry ----
    const float bx1 = boxes[r * 4 + 0];
    const float by1 = boxes[r * 4 + 1];
    const float bx2 = boxes[r * 4 + 2];
    const float by2 = boxes[r * 4 + 3];

    const float area = (bx2 - bx1) * (by2 - by1);
    float lvf = floorf(4.0f + log2f(sqrtf(area) / 224.0f + 1e-6f));
    lvf = fminf(fmaxf(lvf, 2.0f), 5.0f);
    const int level = (int)lvf - 2;

    const int   Htab[NLVL]  = {200, 100, 50, 25};
    const float sctab[NLVL] = {0.25f, 0.125f, 0.0625f, 0.03125f};
    const int   H  = Htab[level];
    const int   W  = H;
    const float sc = sctab[level];
    const float* feat = (level == 0) ? f0 : (level == 1) ? f1 : (level == 2) ? f2 : f3;

    const float x1 = bx1 * sc, y1 = by1 * sc;
    const float roi_w = fmaxf(bx2 * sc - x1, 1.0f);
    const float roi_h = fmaxf(by2 * sc - y1, 1.0f);
    const float bin_w = roi_w / 7.0f;
    const float bin_h = roi_h / 7.0f;

    // ---- warp-uniform y geometry for this ph: 4 rows + folded weights ----
    int   Ry[4];
    float CyW[4];
    #pragma unroll
    for (int s = 0; s < 2; s++) {
        const float g = (float)ph + ((float)s + 0.5f) * 0.5f;
        float pos = y1 + g * bin_h;
        const float vld = (pos >= -1.0f && pos <= (float)H) ? 0.25f : 0.0f;  // fold /4
        pos = fmaxf(pos, 0.0f);
        int lo = (int)pos, hi;
        if (lo >= H - 1) { lo = H - 1; hi = H - 1; pos = (float)lo; }
        else             { hi = lo + 1; }
        const float fr = pos - (float)lo;
        Ry[2 * s + 0] = lo * W;
        Ry[2 * s + 1] = hi * W;
        CyW[2 * s + 0] = vld * (1.0f - fr);
        CyW[2 * s + 1] = vld * fr;
    }

    // ---- per-lane x geometry: pw = lane>>2, j = lane&3 -> (sample, side) ----
    const int  pw   = lane >> 2;
    const int  j    = lane & 3;
    const bool live = (pw < 7);
    int   col = 0;
    float cxw = 0.0f;
    if (live) {
        const int sx   = j >> 1;
        const int side = j & 1;
        const float g = (float)pw + ((float)sx + 0.5f) * 0.5f;
        float pos = x1 + g * bin_w;
        const float vld = (pos >= -1.0f && pos <= (float)W) ? 1.0f : 0.0f;
        pos = fmaxf(pos, 0.0f);
        int lo = (int)pos, hi;
        if (lo >= W - 1) { lo = W - 1; hi = W - 1; pos = (float)lo; }
        else             { hi = lo + 1; }
        const float fr = pos - (float)lo;
        col = side ? hi : lo;
        cxw = vld * (side ? fr : (1.0f - fr));
    }

    const bool storer = live && (j == 0);

    // ---- sweep 64 channels, x4 unrolled ----
    const size_t plane = (size_t)H * W;
    const int c0 = cq * 64;
    const float* fp = feat + ((size_t)b * 256 + c0) * plane;
    float* op = out + ((size_t)r * 256 + c0) * 49 + ph * 7;

    #pragma unroll 1
    for (int k = 0; k < 64; k += 4) {
        const float* A = fp;
        const float* B = fp + plane;
        const float* C = fp + 2 * plane;
        const float* D = fp + 3 * plane;

        float ta = 0.0f, tb = 0.0f, tc = 0.0f, td = 0.0f;
        if (live) {
            ta = cxw * (CyW[0] * A[Ry[0] + col] + CyW[1] * A[Ry[1] + col]
                      + CyW[2] * A[Ry[2] + col] + CyW[3] * A[Ry[3] + col]);
            tb = cxw * (CyW[0] * B[Ry[0] + col] + CyW[1] * B[Ry[1] + col]
                      + CyW[2] * B[Ry[2] + col] + CyW[3] * B[Ry[3] + col]);
            tc = cxw * (CyW[0] * C[Ry[0] + col] + CyW[1] * C[Ry[1] + col]
                      + CyW[2] * C[Ry[2] + col] + CyW[3] * C[Ry[3] + col]);
            td = cxw * (CyW[0] * D[Ry[0] + col] + CyW[1] * D[Ry[1] + col]
                      + CyW[2] * D[Ry[2] + col] + CyW[3] * D[Ry[3] + col]);
        }
        // reduce the 4 x-taps of each bin (xor stays within aligned quads)
        ta += __shfl_xor_sync(0xFFFFFFFFu, ta, 1);
        tb += __shfl_xor_sync(0xFFFFFFFFu, tb, 1);
        tc += __shfl_xor_sync(0xFFFFFFFFu, tc, 1);
        td += __shfl_xor_sync(0xFFFFFFFFu, td, 1);
        ta += __shfl_xor_sync(0xFFFFFFFFu, ta, 2);
        tb += __shfl_xor_sync(0xFFFFFFFFu, tb, 2);
        tc += __shfl_xor_sync(0xFFFFFFFFu, tc, 2);
        td += __shfl_xor_sync(0xFFFFFFFFu, td, 2);

        if (storer) {
            op[pw]           = ta;
            op[49 + pw]      = tb;
            op[2 * 49 + pw]  = tc;
            op[3 * 49 + pw]  = td;
        }
        fp += 4 * plane;
        op += 4 * 49;
    }
}

extern "C" void kernel_launch(void* const* d_in, const int* in_sizes, int n_in,
                              void* d_out, int out_size) {
    const int nroi = in_sizes[4] / 4;   // 512
    roi_align_kernel<<<nroi * 4, 224>>>(
        (const float*)d_in[0], (const float*)d_in[1],
        (const float*)d_in[2], (const float*)d_in[3],
        (const float*)d_in[4], (float*)d_out);
}

// round 16
// speedup vs baseline: 1.1374x; 1.1374x over previous
#include <cuda_runtime.h>

// MultiScaleRoIAlign: 4-level FPN, RoIAlign(aligned=False), OUT=7, SR=2.
// feats: [2,256,200,200],[2,256,100,100],[2,256,50,50],[2,256,25,25] fp32
// boxes: [2,256,4] fp32 -> out: [512,256,7,7] fp32
//
// v16: fixed v15. grid = 2048 (4 blocks/RoI, 64 ch each), block = 224
// (7 warps), warp = bin row ph. Lane = (half, pw, sy): lanes 0..13 ->
// channel stream A, 16..29 -> stream B; within a half, pw = l>>1, sy = l&1.
// Each lane integrates its y-sample over BOTH x-samples (2 rows x 4 cols =
// 8 cells, 8 combined register weights); shfl_xor(1) merges sy=0/1.
// x2 channel unroll per stream.

#define NLVL 4

__global__ __launch_bounds__(224) void roi_align_kernel(
    const float* __restrict__ f0, const float* __restrict__ f1,
    const float* __restrict__ f2, const float* __restrict__ f3,
    const float* __restrict__ boxes, float* __restrict__ out)
{
    const int blk  = blockIdx.x;
    const int r    = blk >> 2;         // roi 0..511
    const int cq   = blk & 3;          // channel quarter (64 ch)
    const int tid  = threadIdx.x;
    const int ph   = tid >> 5;         // warp 0..6 = bin row
    const int lane = tid & 31;
    const int half = lane >> 4;        // 0: stream A, 1: stream B
    const int l    = lane & 15;        // 0..15; live if < 14
    const int b    = r >> 8;

    // ---- per-RoI geometry ----
    const float bx1 = boxes[r * 4 + 0];
    const float by1 = boxes[r * 4 + 1];
    const float bx2 = boxes[r * 4 + 2];
    const float by2 = boxes[r * 4 + 3];

    const float area = (bx2 - bx1) * (by2 - by1);
    float lvf = floorf(4.0f + log2f(sqrtf(area) / 224.0f + 1e-6f));
    lvf = fminf(fmaxf(lvf, 2.0f), 5.0f);
    const int level = (int)lvf - 2;

    const int   Htab[NLVL]  = {200, 100, 50, 25};
    const float sctab[NLVL] = {0.25f, 0.125f, 0.0625f, 0.03125f};
    const int   H  = Htab[level];
    const int   W  = H;
    const float sc = sctab[level];
    const float* feat = (level == 0) ? f0 : (level == 1) ? f1 : (level == 2) ? f2 : f3;

    const float x1 = bx1 * sc, y1 = by1 * sc;
    const float roi_w = fmaxf(bx2 * sc - x1, 1.0f);
    const float roi_h = fmaxf(by2 * sc - y1, 1.0f);
    const float bin_w = roi_w / 7.0f;
    const float bin_h = roi_h / 7.0f;

    // ---- this lane: bin (ph, pw), y-sample sy ----
    const bool live = (l < 14);
    const int  pw = live ? (l >> 1) : 0;
    const int  sy = l & 1;

    // y tap (jy = 2*ph + sy), validity and /4 folded
    int yloW, yhiW; float wy0, wy1;
    {
        const float g = (float)ph + ((float)sy + 0.5f) * 0.5f;
        float pos = y1 + g * bin_h;
        const float vld = (pos >= -1.0f && pos <= (float)H) ? 0.25f : 0.0f;
        pos = fmaxf(pos, 0.0f);
        int lo = (int)pos, hi;
        if (lo >= H - 1) { lo = H - 1; hi = H - 1; pos = (float)lo; }
        else             { hi = lo + 1; }
        const float fr = pos - (float)lo;
        yloW = lo * W; yhiW = hi * W;
        wy0 = vld * (1.0f - fr); wy1 = vld * fr;
    }

    // x taps for BOTH x-samples (jx = 2*pw + sx, sx = 0,1)
    int   xc[4];
    float wx[4];
    #pragma unroll
    for (int sx = 0; sx < 2; sx++) {
        const float g = (float)pw + ((float)sx + 0.5f) * 0.5f;
        float pos = x1 + g * bin_w;
        const float vld = (pos >= -1.0f && pos <= (float)W) ? 1.0f : 0.0f;
        pos = fmaxf(pos, 0.0f);
        int lo = (int)pos, hi;
        if (lo >= W - 1) { lo = W - 1; hi = W - 1; pos = (float)lo; }
        else             { hi = lo + 1; }
        const float fr = pos - (float)lo;
        xc[2 * sx + 0] = lo;  wx[2 * sx + 0] = vld * (1.0f - fr);
        xc[2 * sx + 1] = hi;  wx[2 * sx + 1] = vld * fr;
    }

    // 8 cell offsets + 8 combined weights, register-resident
    int   o[8];
    float c[8];
    #pragma unroll
    for (int jj = 0; jj < 4; jj++) {
        o[jj]     = yloW + xc[jj];  c[jj]     = wy0 * wx[jj];
        o[4 + jj] = yhiW + xc[jj];  c[4 + jj] = wy1 * wx[jj];
    }

    const bool storer = live && (sy == 0);

    // ---- sweep: half h covers channels [c0, c0+32) ----
    const size_t plane = (size_t)H * W;
    const int c0 = cq * 64 + half * 32;
    const float* fp = feat + ((size_t)b * 256 + c0) * plane;
    float* op = out + ((size_t)r * 256 + c0) * 49 + ph * 7 + pw;

    #pragma unroll 1
    for (int k = 0; k < 32; k += 2) {
        const float* A = fp;
        const float* B = fp + plane;

        float ta = 0.0f, tb = 0.0f;
        #pragma unroll
        for (int i = 0; i < 8; i++) {
            ta += c[i] * A[o[i]];
            tb += c[i] * B[o[i]];
        }

        // merge the two y-samples (lanes l, l^1 share the same pw)
        ta += __shfl_xor_sync(0xFFFFFFFFu, ta, 1);
        tb += __shfl_xor_sync(0xFFFFFFFFu, tb, 1);

        if (storer) {
            op[0]  = ta;
            op[49] = tb;
        }
        fp += 2 * plane;
        op += 2 * 49;
    }
}

extern "C" void kernel_launch(void* const* d_in, const int* in_sizes, int n_in,
                              void* d_out, int out_size) {
    const int nroi = in_sizes[4] / 4;   // 512
    roi_align_kernel<<<nroi * 4, 224>>>(
        (const float*)d_in[0], (const float*)d_in[1],
        (const float*)d_in[2], (const float*)d_in[3],
        (const float*)d_in[4], (float*)d_out);
}

// round 17
// speedup vs baseline: 1.1710x; 1.0296x over previous
#include <cuda_runtime.h>

// MultiScaleRoIAlign: 4-level FPN, RoIAlign(aligned=False), OUT=7, SR=2.
// feats: [2,256,200,200],[2,256,100,100],[2,256,50,50],[2,256,25,25] fp32
// boxes: [2,256,4] fp32 -> out: [512,256,7,7] fp32
//
// v17: sample-per-lane, 4 lanes per bin, ONE channel per warp-iteration.
// grid = 2048 (4 blocks/RoI, 64 ch each), block = 224 (7 warps),
// warp = bin row ph. lane = pw*4 + j, j = sy*2 + sx (28 live lanes =
// 7 bins x 4 samples). Each lane: 4 register cell offsets + 4 folded
// weights for its sample; shfl_xor(1)+shfl_xor(2) reduce the quad;
// lane j==0 stores. x4 channel unroll for MLP=16.

#define NLVL 4

__global__ __launch_bounds__(224) void roi_align_kernel(
    const float* __restrict__ f0, const float* __restrict__ f1,
    const float* __restrict__ f2, const float* __restrict__ f3,
    const float* __restrict__ boxes, float* __restrict__ out)
{
    const int blk  = blockIdx.x;
    const int r    = blk >> 2;         // roi 0..511
    const int cq   = blk & 3;          // channel quarter (64 ch)
    const int tid  = threadIdx.x;
    const int ph   = tid >> 5;         // warp 0..6 = bin row
    const int lane = tid & 31;
    const int b    = r >> 8;

    // ---- per-RoI geometry ----
    const float bx1 = boxes[r * 4 + 0];
    const float by1 = boxes[r * 4 + 1];
    const float bx2 = boxes[r * 4 + 2];
    const float by2 = boxes[r * 4 + 3];

    const float area = (bx2 - bx1) * (by2 - by1);
    float lvf = floorf(4.0f + log2f(sqrtf(area) / 224.0f + 1e-6f));
    lvf = fminf(fmaxf(lvf, 2.0f), 5.0f);
    const int level = (int)lvf - 2;

    const int   Htab[NLVL]  = {200, 100, 50, 25};
    const float sctab[NLVL] = {0.25f, 0.125f, 0.0625f, 0.03125f};
    const int   H  = Htab[level];
    const int   W  = H;
    const float sc = sctab[level];
    const float* feat = (level == 0) ? f0 : (level == 1) ? f1 : (level == 2) ? f2 : f3;

    const float x1 = bx1 * sc, y1 = by1 * sc;
    const float roi_w = fmaxf(bx2 * sc - x1, 1.0f);
    const float roi_h = fmaxf(by2 * sc - y1, 1.0f);
    const float bin_w = roi_w / 7.0f;
    const float bin_h = roi_h / 7.0f;

    // ---- this lane's sample: bin (ph, pw), sample (sy, sx) ----
    const bool live = (lane < 28);
    const int  pw = live ? (lane >> 2) : 0;
    const int  j  = lane & 3;
    const int  sy = j >> 1;
    const int  sx = j & 1;

    // y tap (jy = 2*ph + sy), validity and /4 folded
    int yloW, yhiW; float wy0, wy1;
    {
        const float g = (float)ph + ((float)sy + 0.5f) * 0.5f;
        float pos = y1 + g * bin_h;
        const float vld = (pos >= -1.0f && pos <= (float)H) ? 0.25f : 0.0f;
        pos = fmaxf(pos, 0.0f);
        int lo = (int)pos, hi;
        if (lo >= H - 1) { lo = H - 1; hi = H - 1; pos = (float)lo; }
        else             { hi = lo + 1; }
        const float fr = pos - (float)lo;
        yloW = lo * W; yhiW = hi * W;
        wy0 = vld * (1.0f - fr); wy1 = vld * fr;
    }
    // x tap (jx = 2*pw + sx)
    int xlo, xhi; float wx0, wx1;
    {
        const float g = (float)pw + ((float)sx + 0.5f) * 0.5f;
        float pos = x1 + g * bin_w;
        const float vld = (pos >= -1.0f && pos <= (float)W) ? 1.0f : 0.0f;
        pos = fmaxf(pos, 0.0f);
        int lo = (int)pos, hi;
        if (lo >= W - 1) { lo = W - 1; hi = W - 1; pos = (float)lo; }
        else             { hi = lo + 1; }
        const float fr = pos - (float)lo;
        xlo = lo; xhi = hi;
        wx0 = vld * (1.0f - fr); wx1 = vld * fr;
    }

    // 4 cell offsets + 4 combined weights for this sample
    const int   o00 = yloW + xlo, o01 = yloW + xhi;
    const int   o10 = yhiW + xlo, o11 = yhiW + xhi;
    const float c00 = wy0 * wx0, c01 = wy0 * wx1;
    const float c10 = wy1 * wx0, c11 = wy1 * wx1;

    const bool storer = live && (j == 0);

    // ---- sweep 64 channels, x4 unrolled ----
    const size_t plane = (size_t)H * W;
    const int c0 = cq * 64;
    const float* fp = feat + ((size_t)b * 256 + c0) * plane;
    float* op = out + ((size_t)r * 256 + c0) * 49 + ph * 7 + pw;

    #pragma unroll 1
    for (int k = 0; k < 64; k += 4) {
        const float* A = fp;
        const float* B = fp + plane;
        const float* C = fp + 2 * plane;
        const float* D = fp + 3 * plane;

        float ta = 0.0f, tb = 0.0f, tc = 0.0f, td = 0.0f;
        if (live) {
            ta = c00 * A[o00] + c01 * A[o01] + c10 * A[o10] + c11 * A[o11];
            tb = c00 * B[o00] + c01 * B[o01] + c10 * B[o10] + c11 * B[o11];
            tc = c00 * C[o00] + c01 * C[o01] + c10 * C[o10] + c11 * C[o11];
            td = c00 * D[o00] + c01 * D[o01] + c10 * D[o10] + c11 * D[o11];
        }

        // reduce the 4 samples of each bin (aligned quads)
        ta += __shfl_xor_sync(0xFFFFFFFFu, ta, 1);
        tb += __shfl_xor_sync(0xFFFFFFFFu, tb, 1);
        tc += __shfl_xor_sync(0xFFFFFFFFu, tc, 1);
        td += __shfl_xor_sync(0xFFFFFFFFu, td, 1);
        ta += __shfl_xor_sync(0xFFFFFFFFu, ta, 2);
        tb += __shfl_xor_sync(0xFFFFFFFFu, tb, 2);
        tc += __shfl_xor_sync(0xFFFFFFFFu, tc, 2);
        td += __shfl_xor_sync(0xFFFFFFFFu, td, 2);

        if (storer) {
            op[0]      = ta;
            op[49]     = tb;
            op[2 * 49] = tc;
            op[3 * 49] = td;
        }
        fp += 4 * plane;
        op += 4 * 49;
    }
}

extern "C" void kernel_launch(void* const* d_in, const int* in_sizes, int n_in,
                              void* d_out, int out_size) {
    const int nroi = in_sizes[4] / 4;   // 512
    roi_align_kernel<<<nroi * 4, 224>>>(
        (const float*)d_in[0], (const float*)d_in[1],
        (const float*)d_in[2], (const float*)d_in[3],
        (const float*)d_in[4], (float*)d_out);
}